// round 10
// baseline (speedup 1.0000x reference)
#include <cuda_runtime.h>
#include <cstdint>

#define LEN 4096
#define HH 256
#define NT 194
#define QSTRIDE 4104
// SIDX(4t + c) = 5t + c + (c>>2); OFF(c) is the compile-time/linear part.
#define OFF(c) ((c) + ((c) >> 2))

typedef unsigned long long u64;

__device__ u64 g_Wd[HH * NT * 4];          // [h][T][c] duplicated (w,w) diff-weights
__device__ float g_Q[4096 * QSTRIDE];      // unpadded prefix sums per (b,h) row

__device__ __forceinline__ u64 pk2(float a, float b) {
    u64 r;
    asm("mov.b64 %0, {%1, %2};" : "=l"(r) : "r"(__float_as_uint(a)), "r"(__float_as_uint(b)));
    return r;
}
__device__ __forceinline__ u64 fma2(u64 a, u64 b, u64 c) {
    u64 d;
    asm("fma.rn.f32x2 %0, %1, %2, %3;" : "=l"(d) : "l"(a), "l"(b), "l"(c));
    return d;
}

// ---------------- weight build: difference weights + folded skip, dup pairs ----
// conv[l] = sum_T dw_T * Q[l + 513 - p_T]
// p_T = O_i + m*R_i (T=i*32+m), p_192=1024 (tail), p_193=513 (odd, carries -D)
__global__ void build_weights_kernel(const float* __restrict__ kers,
                                     const float* __restrict__ D) {
    int h = blockIdx.x;
    int c = threadIdx.x >> 5;
    int lane = threadIdx.x & 31;
    const float normw[6] = {1024.f, 256.f, 128.f, 64.f, 32.f, 16.f};
    const float sc[6]    = {32.f, 16.f, 8.f, 4.f, 2.f, 1.f};

    float vals[6];
    float ss = 0.f;
#pragma unroll
    for (int i = 0; i < 6; i++) {
        float v = kers[((i * 4 + c) * HH + h) * 32 + lane];
        vals[i] = v * sc[i];
        ss += v * v * normw[i];
    }
#pragma unroll
    for (int o = 16; o; o >>= 1) ss += __shfl_xor_sync(0xffffffffu, ss, o);
    float inv = 1.0f / sqrtf(ss);
    float dv = D[c * HH + h];

    float lastv = 0.f;
#pragma unroll
    for (int i = 0; i < 6; i++) {
        float nv = vals[i] * inv;
        float up = __shfl_up_sync(0xffffffffu, nv, 1);
        float dw = nv - ((lane == 0) ? lastv : up);
        if (i == 5 && lane == 0) dw += dv;          // p=512 absorbs +D
        g_Wd[(h * NT + i * 32 + lane) * 4 + c] = pk2(dw, dw);
        lastv = __shfl_sync(0xffffffffu, nv, 31);
    }
    if (lane == 0) {
        g_Wd[(h * NT + 192) * 4 + c] = pk2(-lastv, -lastv);  // tail p=1024
        g_Wd[(h * NT + 193) * 4 + c] = pk2(-dv, -dv);        // skip odd p=513
    }
}

// ---------------- scan: prefix sums (no padding) ----------------
__global__ __launch_bounds__(256) void scan_kernel(const float* __restrict__ x) {
    __shared__ float Psh[4097];
    __shared__ float wsum[8];
    int t = threadIdx.x;
    int row = blockIdx.x;
    const float* xr = x + (size_t)row * LEN;

    float vv[16];
#pragma unroll
    for (int u = 0; u < 4; u++) {
        float4 v = *(const float4*)(xr + 16 * t + 4 * u);
        vv[4*u] = v.x; vv[4*u+1] = v.y; vv[4*u+2] = v.z; vv[4*u+3] = v.w;
    }
    float r[16];
    float run = 0.f;
#pragma unroll
    for (int u = 0; u < 16; u++) { run += vv[u]; r[u] = run; }
    float incl = run;
#pragma unroll
    for (int o = 1; o < 32; o <<= 1) {
        float v = __shfl_up_sync(0xffffffffu, incl, o);
        if ((t & 31) >= o) incl += v;
    }
    if ((t & 31) == 31) wsum[t >> 5] = incl;
    __syncthreads();
    float woff = 0.f;
#pragma unroll
    for (int w = 0; w < 8; w++) {
        float v = wsum[w];
        if (w < (t >> 5)) woff += v;
    }
    float e = woff + (incl - run);
    if (t == 0) Psh[0] = 0.f;
#pragma unroll
    for (int u = 0; u < 16; u++) Psh[16 * t + u + 1] = e + r[u];
    __syncthreads();

    float* qr = g_Q + (size_t)row * QSTRIDE;
#pragma unroll
    for (int u = 0; u < 16; u++) qr[t + 256 * u] = Psh[t + 256 * u];
    if (t == 0) qr[4096] = Psh[4096];
}

// ---------------- conv ----------------
__device__ __forceinline__ u64 LD2(const float2* p, int off) {
    return *(const u64*)(p + off);
}

__device__ __forceinline__ void mact(u64 acc[4][4], u64 a0, u64 a1, u64 a2, u64 a3,
                                     const u64* __restrict__ Wsh, int T) {
    ulonglong2 w01 = *(const ulonglong2*)(Wsh + 4 * T);
    ulonglong2 w23 = *(const ulonglong2*)(Wsh + 4 * T + 2);
    acc[0][0] = fma2(a0, w01.x, acc[0][0]);
    acc[0][1] = fma2(a1, w01.x, acc[0][1]);
    acc[0][2] = fma2(a2, w01.x, acc[0][2]);
    acc[0][3] = fma2(a3, w01.x, acc[0][3]);
    acc[1][0] = fma2(a0, w01.y, acc[1][0]);
    acc[1][1] = fma2(a1, w01.y, acc[1][1]);
    acc[1][2] = fma2(a2, w01.y, acc[1][2]);
    acc[1][3] = fma2(a3, w01.y, acc[1][3]);
    acc[2][0] = fma2(a0, w23.x, acc[2][0]);
    acc[2][1] = fma2(a1, w23.x, acc[2][1]);
    acc[2][2] = fma2(a2, w23.x, acc[2][2]);
    acc[2][3] = fma2(a3, w23.x, acc[2][3]);
    acc[3][0] = fma2(a0, w23.y, acc[3][0]);
    acc[3][1] = fma2(a1, w23.y, acc[3][1]);
    acc[3][2] = fma2(a2, w23.y, acc[3][2]);
    acc[3][3] = fma2(a3, w23.y, acc[3][3]);
}

// One CTA per (row, half). Thread owns 8 consecutive l: pairs 4t..4t+3 (+L0).
// Window W[i] = Q[L0-512+i] (clamped). PE[k]=(W[2k],W[2k+1]); PO[k]=(W[2k+1],W[2k+2]).
// Tap p: pair index c = j + K, K = (1024-p)/2 (even p, PO) or (1025-p)/2 (odd p, PE).
// Smem layout SIDX(4t+c) = 5t + OFF(c) -> stride-5-pair, conflict-free, [R+imm] addressing.
__global__ __launch_bounds__(256, 3) void conv_kernel(float* __restrict__ out) {
    __shared__ float2 PE[1920];
    __shared__ float2 PO[1920];
    __shared__ __align__(16) u64 Wsh[NT * 4];

    const int t = threadIdx.x;
    const int row = blockIdx.x >> 1;
    const int L0 = (blockIdx.x & 1) * 2048;
    const int h = row & 255;

    // fill window pair arrays (k in [0,1536)), clamped gmem reads
    const float* qr = g_Q + (size_t)row * QSTRIDE;
    const int gbase = L0 - 512;
#pragma unroll
    for (int v = 0; v < 6; v++) {
        int k = t + 256 * v;
        int i0 = gbase + 2 * k;
        float a0 = qr[min(max(i0,     0), 4096)];
        float a1 = qr[min(max(i0 + 1, 0), 4096)];
        float a2 = qr[min(max(i0 + 2, 0), 4096)];
        int sk = k + (k >> 2);
        PE[sk] = make_float2(a0, a1);
        PO[sk] = make_float2(a1, a2);
    }
    {
        const u64* ws = g_Wd + h * (NT * 4);
#pragma unroll
        for (int v = 0; v < 4; v++) {
            int i = t + 256 * v;
            if (i < NT * 4) Wsh[i] = ws[i];
        }
    }
    __syncthreads();

    const float2* PEb = PE + 5 * t;
    const float2* POb = PO + 5 * t;
    u64 acc[4][4] = {};
    u64 q0, q1, q2, q3, nt;

    // ======== ODD sweep (PE): taps s=0..31, K=512-s, T=2s+1 ========
    q0 = LD2(PEb, OFF(512)); q1 = LD2(PEb, OFF(513));
    q2 = LD2(PEb, OFF(514)); q3 = LD2(PEb, OFF(515));
    {
        const float2* p = PEb;
#pragma unroll 1
        for (int i = 0; i < 8; i++) {
            int T = 8 * i + 1;
            nt = q3; q3 = LD2(p, 638); mact(acc, q0, q1, q2, nt, Wsh, T);
            nt = q2; q2 = LD2(p, 637); mact(acc, q3, q0, q1, nt, Wsh, T + 2);
            nt = q1; q1 = LD2(p, 636); mact(acc, q2, q3, q0, nt, Wsh, T + 4);
            nt = q0; q0 = LD2(p, 635); mact(acc, q1, q2, q3, nt, Wsh, T + 6);
            p -= 5;
        }
    }
    // skip tap p=513: K=256, T=193
    q0 = LD2(PEb, OFF(256)); q1 = LD2(PEb, OFF(257));
    q2 = LD2(PEb, OFF(258)); q3 = LD2(PEb, OFF(259));
    mact(acc, q0, q1, q2, q3, Wsh, 193);

    // ======== EVEN sweep (PO) ========
    q0 = LD2(POb, OFF(512)); q1 = LD2(POb, OFF(513));
    q2 = LD2(POb, OFF(514)); q3 = LD2(POb, OFF(515));
    {
        const float2* p = POb;
        // s=0..31: T=2s
#pragma unroll 1
        for (int i = 0; i < 8; i++) {
            int T = 8 * i;
            nt = q3; q3 = LD2(p, 638); mact(acc, q0, q1, q2, nt, Wsh, T);
            nt = q2; q2 = LD2(p, 637); mact(acc, q3, q0, q1, nt, Wsh, T + 2);
            nt = q1; q1 = LD2(p, 636); mact(acc, q2, q3, q0, nt, Wsh, T + 4);
            nt = q0; q0 = LD2(p, 635); mact(acc, q1, q2, q3, nt, Wsh, T + 6);
            p -= 5;
        }
        // s=32..63: T=32+s = 64 + (s-32)
#pragma unroll 1
        for (int i = 0; i < 8; i++) {
            int T = 64 + 4 * i;
            nt = q3; q3 = LD2(p, 638); mact(acc, q0, q1, q2, nt, Wsh, T);
            nt = q2; q2 = LD2(p, 637); mact(acc, q3, q0, q1, nt, Wsh, T + 1);
            nt = q1; q1 = LD2(p, 636); mact(acc, q2, q3, q0, nt, Wsh, T + 2);
            nt = q0; q0 = LD2(p, 635); mact(acc, q1, q2, q3, nt, Wsh, T + 3);
            p -= 5;
        }
    }
    // window now [448..451] in slots q0..q3

    // ---- scale 3 (step 2): m=0..31, K=448-2m, T=96+m ----
    {
        const float2* p = POb;
        u64 t2, t3;
#pragma unroll 1
        for (int i = 0; i < 16; i++) {
            int T = 96 + 2 * i;
            t2 = q2; t3 = q3;
            q2 = LD2(p, 557); q3 = LD2(p, 558);
            mact(acc, q0, q1, t2, t3, Wsh, T);
            t2 = q0; t3 = q1;
            q0 = LD2(p, 555); q1 = LD2(p, 556);
            mact(acc, q2, q3, t2, t3, Wsh, T + 1);
            p -= 5;
        }
    }
    // window now [384..387] in q0..q3

    // ---- scale 4 (step 4): m=0..31, K=384-4m, T=128+m, ping-pong ----
    {
        const float2* p = POb;
        u64 r0, r1, r2, r3;
#pragma unroll 1
        for (int i = 0; i < 16; i++) {
            int T = 128 + 2 * i;
            r0 = LD2(p, 475); r1 = LD2(p, 476); r2 = LD2(p, 477); r3 = LD2(p, 478);
            mact(acc, q0, q1, q2, q3, Wsh, T);
            q0 = LD2(p, 470); q1 = LD2(p, 471); q2 = LD2(p, 472); q3 = LD2(p, 473);
            mact(acc, r0, r1, r2, r3, Wsh, T + 1);
            p -= 10;
        }
    }
    // window now [256..259] in q0..q3

    // ---- scale 5 (step 8): m=0..31, K=256-8m, T=160+m, ping-pong ----
    {
        const float2* p = POb;
        u64 r0, r1, r2, r3;
#pragma unroll 1
        for (int i = 0; i < 16; i++) {
            int T = 160 + 2 * i;
            r0 = LD2(p, 310); r1 = LD2(p, 311); r2 = LD2(p, 312); r3 = LD2(p, 313);
            mact(acc, q0, q1, q2, q3, Wsh, T);
            q0 = LD2(p, 300); q1 = LD2(p, 301); q2 = LD2(p, 302); q3 = LD2(p, 303);
            mact(acc, r0, r1, r2, r3, Wsh, T + 1);
            p -= 20;
        }
    }
    // window now [0..3] in q0..q3: tail p=1024, T=192
    mact(acc, q0, q1, q2, q3, Wsh, 192);

    // ---- output: out[(row*4+c)*4096 + L0 + 8t + {0..7}] ----
    float* outb = out + (size_t)row * 4 * LEN + L0 + 8 * t;
#pragma unroll
    for (int c = 0; c < 4; c++) {
        ulonglong2* oc = (ulonglong2*)(outb + (size_t)c * LEN);
        oc[0] = make_ulonglong2(acc[c][0], acc[c][1]);
        oc[1] = make_ulonglong2(acc[c][2], acc[c][3]);
    }
}

extern "C" void kernel_launch(void* const* d_in, const int* in_sizes, int n_in,
                              void* d_out, int out_size)
{
    const float* x    = (const float*)d_in[0];
    const float* kers = (const float*)d_in[1];
    const float* D    = (const float*)d_in[2];
    float* out = (float*)d_out;

    build_weights_kernel<<<HH, 128>>>(kers, D);
    scan_kernel<<<4096, 256>>>(x);
    conv_kernel<<<8192, 256>>>(out);
}

// round 12
// speedup vs baseline: 1.1913x; 1.1913x over previous
#include <cuda_runtime.h>
#include <cstdint>

#define LEN 4096
#define HH 256
#define NT 194
// SIDX(4t + c) = 5t + c + (c>>2); OFF(c) is the compile-time/linear part.
#define OFF(c) ((c) + ((c) >> 2))

typedef unsigned long long u64;

__device__ float g_W[HH * NT * 4];      // [h][T][c] difference weights (float4 rows)

__device__ __forceinline__ u64 pk2(float a, float b) {
    u64 r;
    asm("mov.b64 %0, {%1, %2};" : "=l"(r) : "r"(__float_as_uint(a)), "r"(__float_as_uint(b)));
    return r;
}
__device__ __forceinline__ u64 fma2(u64 a, u64 b, u64 c) {
    u64 d;
    asm("fma.rn.f32x2 %0, %1, %2, %3;" : "=l"(d) : "l"(a), "l"(b), "l"(c));
    return d;
}

// ---------------- weight build: difference weights + folded skip ----------------
// conv[l] = sum_T dw_T * Q[l + 513 - p_T]
// p_T = O_i + m*R_i (T=i*32+m), p_192=1024 (tail), p_193=513 (odd, carries -D)
// NOTE: sum_T dw_T == 0, so conv is invariant to constant shifts of Q.
__global__ void build_weights_kernel(const float* __restrict__ kers,
                                     const float* __restrict__ D) {
    int h = blockIdx.x;
    int c = threadIdx.x >> 5;
    int lane = threadIdx.x & 31;
    const float normw[6] = {1024.f, 256.f, 128.f, 64.f, 32.f, 16.f};
    const float sc[6]    = {32.f, 16.f, 8.f, 4.f, 2.f, 1.f};

    float vals[6];
    float ss = 0.f;
#pragma unroll
    for (int i = 0; i < 6; i++) {
        float v = kers[((i * 4 + c) * HH + h) * 32 + lane];
        vals[i] = v * sc[i];
        ss += v * v * normw[i];
    }
#pragma unroll
    for (int o = 16; o; o >>= 1) ss += __shfl_xor_sync(0xffffffffu, ss, o);
    float inv = 1.0f / sqrtf(ss);
    float dv = D[c * HH + h];

    float lastv = 0.f;
#pragma unroll
    for (int i = 0; i < 6; i++) {
        float nv = vals[i] * inv;
        float up = __shfl_up_sync(0xffffffffu, nv, 1);
        float dw = nv - ((lane == 0) ? lastv : up);
        if (i == 5 && lane == 0) dw += dv;          // p=512 absorbs +D
        g_W[(h * NT + i * 32 + lane) * 4 + c] = dw;
        lastv = __shfl_sync(0xffffffffu, nv, 31);
    }
    if (lane == 0) {
        g_W[(h * NT + 192) * 4 + c] = -lastv;       // tail p=1024
        g_W[(h * NT + 193) * 4 + c] = -dv;          // skip odd p=513
    }
}

// ---------------- conv (fused local scan) ----------------
__device__ __forceinline__ u64 LD2(const float2* p, int off) {
    return *(const u64*)(p + off);
}

__device__ __forceinline__ void mact(u64 acc[4][4], u64 a0, u64 a1, u64 a2, u64 a3,
                                     const float4* __restrict__ Wsh, int T) {
    float4 w = Wsh[T];
    u64 w0 = pk2(w.x, w.x);
    u64 w1 = pk2(w.y, w.y);
    u64 w2 = pk2(w.z, w.z);
    u64 w3 = pk2(w.w, w.w);
    acc[0][0] = fma2(a0, w0, acc[0][0]);
    acc[0][1] = fma2(a1, w0, acc[0][1]);
    acc[0][2] = fma2(a2, w0, acc[0][2]);
    acc[0][3] = fma2(a3, w0, acc[0][3]);
    acc[1][0] = fma2(a0, w1, acc[1][0]);
    acc[1][1] = fma2(a1, w1, acc[1][1]);
    acc[1][2] = fma2(a2, w1, acc[1][2]);
    acc[1][3] = fma2(a3, w1, acc[1][3]);
    acc[2][0] = fma2(a0, w2, acc[2][0]);
    acc[2][1] = fma2(a1, w2, acc[2][1]);
    acc[2][2] = fma2(a2, w2, acc[2][2]);
    acc[2][3] = fma2(a3, w2, acc[2][3]);
    acc[3][0] = fma2(a0, w3, acc[3][0]);
    acc[3][1] = fma2(a1, w3, acc[3][1]);
    acc[3][2] = fma2(a2, w3, acc[3][2]);
    acc[3][3] = fma2(a3, w3, acc[3][3]);
}

// One CTA per (row, half). Thread owns 8 consecutive l: pairs 4t..4t+3 (+L0).
// Window W[i] = local prefix of xw over [j0, j0+3072), j0 = L0-512, xw zero-filled
// outside [0,4096). Equals Q[clamp(j0+i)] - Q[clamp(j0)]; valid since sum(dw)=0.
// PE[k]=(W[2k],W[2k+1]); PO[k]=(W[2k+1],W[2k+2]), k in [0,1536), SIDX-padded.
__global__ __launch_bounds__(256, 3) void conv_kernel(const float* __restrict__ x,
                                                      float* __restrict__ out) {
    __shared__ float2 PE[1920];
    __shared__ float2 PO[1920];
    __shared__ float4 Wsh[NT];
    __shared__ float wsum[8];

    const int t = threadIdx.x;
    const int row = blockIdx.x >> 1;
    const int L0 = (blockIdx.x & 1) * 2048;
    const int h = row & 255;

    // ---- load 12 window x-values (float4-aligned, zero-filled OOB) ----
    const float* xr = x + (size_t)row * LEN;
    const int j0 = L0 - 512;
    float v[12];
#pragma unroll
    for (int u = 0; u < 3; u++) {
        int j = j0 + 12 * t + 4 * u;            // multiple of 4
        float4 f = (j >= 0 && j < LEN) ? *(const float4*)(xr + j)
                                       : make_float4(0.f, 0.f, 0.f, 0.f);
        v[4*u] = f.x; v[4*u+1] = f.y; v[4*u+2] = f.z; v[4*u+3] = f.w;
    }
    if (t < NT) Wsh[t] = *(const float4*)(g_W + (h * NT + t) * 4);

    // ---- local scan: thread-running sums + warp scan + cross-warp ----
    float r[12];
    float run = 0.f;
#pragma unroll
    for (int u = 0; u < 12; u++) { run += v[u]; r[u] = run; }
    float incl = run;
#pragma unroll
    for (int o = 1; o < 32; o <<= 1) {
        float s = __shfl_up_sync(0xffffffffu, incl, o);
        if ((t & 31) >= o) incl += s;
    }
    if ((t & 31) == 31) wsum[t >> 5] = incl;
    __syncthreads();
    float woff = 0.f;
#pragma unroll
    for (int w = 0; w < 8; w++) {
        if (w < (t >> 5)) woff += wsum[w];
    }
    float e = woff + (incl - run);               // W[12t] (exclusive)

    // ---- write pair arrays: thread owns k = 6t..6t+5 ----
    float wv[13];
    wv[0] = e;
#pragma unroll
    for (int u = 0; u < 12; u++) wv[u + 1] = e + r[u];
#pragma unroll
    for (int u = 0; u < 6; u++) {
        int k = 6 * t + u;
        int sk = k + (k >> 2);
        PE[sk] = make_float2(wv[2*u],     wv[2*u + 1]);
        PO[sk] = make_float2(wv[2*u + 1], wv[2*u + 2]);
    }
    __syncthreads();

    const float2* PEb = PE + 5 * t;
    const float2* POb = PO + 5 * t;
    u64 acc[4][4] = {};
    u64 q0, q1, q2, q3, nt;

    // ======== ODD sweep (PE): taps s=0..31, K=512-s, T=2s+1 ========
    q0 = LD2(PEb, OFF(512)); q1 = LD2(PEb, OFF(513));
    q2 = LD2(PEb, OFF(514)); q3 = LD2(PEb, OFF(515));
    {
        const float2* p = PEb;
#pragma unroll 1
        for (int i = 0; i < 8; i++) {
            int T = 8 * i + 1;
            nt = q3; q3 = LD2(p, 638); mact(acc, q0, q1, q2, nt, Wsh, T);
            nt = q2; q2 = LD2(p, 637); mact(acc, q3, q0, q1, nt, Wsh, T + 2);
            nt = q1; q1 = LD2(p, 636); mact(acc, q2, q3, q0, nt, Wsh, T + 4);
            nt = q0; q0 = LD2(p, 635); mact(acc, q1, q2, q3, nt, Wsh, T + 6);
            p -= 5;
        }
    }
    // skip tap p=513: K=256, T=193
    q0 = LD2(PEb, OFF(256)); q1 = LD2(PEb, OFF(257));
    q2 = LD2(PEb, OFF(258)); q3 = LD2(PEb, OFF(259));
    mact(acc, q0, q1, q2, q3, Wsh, 193);

    // ======== EVEN sweep (PO) ========
    q0 = LD2(POb, OFF(512)); q1 = LD2(POb, OFF(513));
    q2 = LD2(POb, OFF(514)); q3 = LD2(POb, OFF(515));
    {
        const float2* p = POb;
        // s=0..31: T=2s
#pragma unroll 1
        for (int i = 0; i < 8; i++) {
            int T = 8 * i;
            nt = q3; q3 = LD2(p, 638); mact(acc, q0, q1, q2, nt, Wsh, T);
            nt = q2; q2 = LD2(p, 637); mact(acc, q3, q0, q1, nt, Wsh, T + 2);
            nt = q1; q1 = LD2(p, 636); mact(acc, q2, q3, q0, nt, Wsh, T + 4);
            nt = q0; q0 = LD2(p, 635); mact(acc, q1, q2, q3, nt, Wsh, T + 6);
            p -= 5;
        }
        // s=32..63: T=32+s = 64 + (s-32)
#pragma unroll 1
        for (int i = 0; i < 8; i++) {
            int T = 64 + 4 * i;
            nt = q3; q3 = LD2(p, 638); mact(acc, q0, q1, q2, nt, Wsh, T);
            nt = q2; q2 = LD2(p, 637); mact(acc, q3, q0, q1, nt, Wsh, T + 1);
            nt = q1; q1 = LD2(p, 636); mact(acc, q2, q3, q0, nt, Wsh, T + 2);
            nt = q0; q0 = LD2(p, 635); mact(acc, q1, q2, q3, nt, Wsh, T + 3);
            p -= 5;
        }
    }
    // window now [448..451] in slots q0..q3

    // ---- scale 3 (step 2): m=0..31, K=448-2m, T=96+m ----
    {
        const float2* p = POb;
        u64 t2, t3;
#pragma unroll 1
        for (int i = 0; i < 16; i++) {
            int T = 96 + 2 * i;
            t2 = q2; t3 = q3;
            q2 = LD2(p, 557); q3 = LD2(p, 558);
            mact(acc, q0, q1, t2, t3, Wsh, T);
            t2 = q0; t3 = q1;
            q0 = LD2(p, 555); q1 = LD2(p, 556);
            mact(acc, q2, q3, t2, t3, Wsh, T + 1);
            p -= 5;
        }
    }
    // window now [384..387] in q0..q3

    // ---- scale 4 (step 4): m=0..31, K=384-4m, T=128+m, ping-pong ----
    {
        const float2* p = POb;
        u64 r0, r1, r2, r3;
#pragma unroll 1
        for (int i = 0; i < 16; i++) {
            int T = 128 + 2 * i;
            r0 = LD2(p, 475); r1 = LD2(p, 476); r2 = LD2(p, 477); r3 = LD2(p, 478);
            mact(acc, q0, q1, q2, q3, Wsh, T);
            q0 = LD2(p, 470); q1 = LD2(p, 471); q2 = LD2(p, 472); q3 = LD2(p, 473);
            mact(acc, r0, r1, r2, r3, Wsh, T + 1);
            p -= 10;
        }
    }
    // window now [256..259] in q0..q3

    // ---- scale 5 (step 8): m=0..31, K=256-8m, T=160+m, ping-pong ----
    {
        const float2* p = POb;
        u64 r0, r1, r2, r3;
#pragma unroll 1
        for (int i = 0; i < 16; i++) {
            int T = 160 + 2 * i;
            r0 = LD2(p, 310); r1 = LD2(p, 311); r2 = LD2(p, 312); r3 = LD2(p, 313);
            mact(acc, q0, q1, q2, q3, Wsh, T);
            q0 = LD2(p, 300); q1 = LD2(p, 301); q2 = LD2(p, 302); q3 = LD2(p, 303);
            mact(acc, r0, r1, r2, r3, Wsh, T + 1);
            p -= 20;
        }
    }
    // window now [0..3] in q0..q3: tail p=1024, T=192
    mact(acc, q0, q1, q2, q3, Wsh, 192);

    // ---- output: out[(row*4+c)*4096 + L0 + 8t + {0..7}] ----
    float* outb = out + (size_t)row * 4 * LEN + L0 + 8 * t;
#pragma unroll
    for (int c = 0; c < 4; c++) {
        ulonglong2* oc = (ulonglong2*)(outb + (size_t)c * LEN);
        oc[0] = make_ulonglong2(acc[c][0], acc[c][1]);
        oc[1] = make_ulonglong2(acc[c][2], acc[c][3]);
    }
}

extern "C" void kernel_launch(void* const* d_in, const int* in_sizes, int n_in,
                              void* d_out, int out_size)
{
    const float* x    = (const float*)d_in[0];
    const float* kers = (const float*)d_in[1];
    const float* D    = (const float*)d_in[2];
    float* out = (float*)d_out;

    build_weights_kernel<<<HH, 128>>>(kers, D);
    conv_kernel<<<8192, 256>>>(x, out);
}